// round 11
// baseline (speedup 1.0000x reference)
#include <cuda_runtime.h>
#include <cstdint>

#define B_N  32
#define C_IN 64
#define H    192
#define W    192
#define HO   190
#define WO   190
#define OC   128
#define HW   (H*W)

#define XR2  132          // Xs row stride (floats): 132%32=4 -> conflict-free B reads
#define PXWIN 128         // staged px window (32 float4 per channel, shift indexing)

// ---------------- device scratch (static; no allocations allowed) -----------
__device__ float g_valid[B_N][4];
__device__ float g_bsum[B_N][OC];
// A-fragment-ordered weights: [tap][chunk][slab(2)][oct(4)][lane(32)][4]
__device__ __align__(16) float g_wA[9 * 8 * 2 * 4 * 32 * 4];
// pre-transformed input: nan-zeroed, validity-masked, tf32-rounded (channel-major)
__device__ __align__(16) float g_x[(size_t)B_N * C_IN * H * W];

__device__ __forceinline__ bool is_nan_bits(float v) {
    unsigned u = __float_as_uint(v);
    return (u & 0x7fffffffu) > 0x7f800000u;
}
__device__ __forceinline__ unsigned f2tf32(float v) {
    unsigned r;
    asm("cvt.rna.tf32.f32 %0, %1;" : "=r"(r) : "f"(v));
    return r;
}
__device__ __forceinline__ unsigned smem_u32(const void* p) {
    unsigned a;
    asm("{ .reg .u64 t; cvta.to.shared.u64 t, %1; cvt.u32.u64 %0, t; }" : "=r"(a) : "l"(p));
    return a;
}

#define MMA_TF32(d, a, b0, b1) \
    asm volatile("mma.sync.aligned.m16n8k8.row.col.f32.tf32.tf32.f32 " \
        "{%0,%1,%2,%3},{%4,%5,%6,%7},{%8,%9},{%0,%1,%2,%3};" \
        : "+f"((d)[0]), "+f"((d)[1]), "+f"((d)[2]), "+f"((d)[3]) \
        : "r"((a).x), "r"((a).y), "r"((a).z), "r"((a).w), "r"(b0), "r"(b1))

// ---------------- setup: validity + bias + fragment-ordered weights ---------
__global__ void setup_kernel(const float* __restrict__ x,
                             const float* __restrict__ w,
                             const float* __restrict__ bias) {
    int t = threadIdx.x;
    if (blockIdx.x < 288) {
        int i = blockIdx.x * 256 + t;            // 0..73727
        int a    = i & 3;
        int lane = (i >> 2) & 31;
        int oct  = (i >> 7) & 3;
        int slab = (i >> 9) & 1;
        int chunk= (i >> 10) & 7;
        int tap  = i >> 13;                      // ky*3 + kx
        // A frag (m16n8k8 tf32): a0:(m,k) a1:(m+8,k) a2:(m,k+4) a3:(m+8,k+4)
        int row  = (lane >> 2) + (a & 1) * 8;
        int kcol = (lane & 3) + (a >> 1) * 4;
        int oc   = slab * 64 + oct * 16 + row;
        int c    = chunk * 8 + kcol;             // raw channel index
        int f = c & 3, j = c >> 2;
        float v = w[f * 18432 + oc * 144 + j * 9 + tap];
        g_wA[i] = __uint_as_float(f2tf32(v));
    } else {
        __shared__ float sval[B_N][4];
        if (t < B_N * 4) {
            int b = t >> 2, f = t & 3;
            float v = x[(size_t)(b * C_IN + f) * HW];   // marker at (0,0)
            float val = is_nan_bits(v) ? 0.f : 1.f;
            g_valid[b][f] = val;
            sval[b][f] = val;
        }
        __syncthreads();
        for (int i = t; i < B_N * OC; i += 256) {
            int b = i >> 7, oc = i & 127;
            float s = 0.f;
#pragma unroll
            for (int f = 0; f < 4; f++) s += sval[b][f] * bias[f * OC + oc];
            g_bsum[b][oc] = s;
        }
    }
}

// ---------------- transform: x -> g_x (nan-zero, mask, tf32 round) ----------
// grid = (36, 2048): blockIdx.y = plane (b*64+c), 9216 float4 per plane.
__global__ void transform_kernel(const float* __restrict__ x) {
    int plane = blockIdx.y;
    int b = plane >> 6, c = plane & 63;
    float vmf = g_valid[b][c & 3];
    size_t off4 = (size_t)plane * (HW / 4) + blockIdx.x * 256 + threadIdx.x;
    float4 v = reinterpret_cast<const float4*>(x)[off4];
    float r[4] = {v.x, v.y, v.z, v.w};
#pragma unroll
    for (int j = 0; j < 4; j++) {
        float u = is_nan_bits(r[j]) ? 0.f : r[j];
        r[j] = __uint_as_float(f2tf32(u * vmf));
    }
    reinterpret_cast<float4*>(g_x)[off4] = make_float4(r[0], r[1], r[2], r[3]);
}

// ---------------- main conv: tf32 mma.sync implicit GEMM --------------------
// grid = (2 x-tiles, 190 rows, 32 batches), block = 256 (8 warps)
// Block tile: 128 oc x 96 px. Warp: 64 oc x 24 px (slab=warp&1, quarter=warp>>1).
__global__ void __launch_bounds__(256, 2)
conv_kernel(float* __restrict__ out) {
    extern __shared__ float Xs[];              // [2][64][XR2]
    const unsigned xsb = smem_u32(Xs);

    const int x0  = blockIdx.x * 94;           // output x start (tiles overlap 2)
    const int px0 = blockIdx.x * 64;           // staged window start
    const int xb0 = x0 - px0;                  // 0 or 30
    const int y  = blockIdx.y;
    const int b  = blockIdx.z;

    const int t    = threadIdx.x;
    const int warp = t >> 5;
    const int lane = t & 31;
    const int slab = warp & 1;                 // oc half (64 oc)
    const int nb   = (warp >> 1) * 24;         // px quarter

    const int cst = t >> 5;                    // (unused helper removed)
    (void)cst;

    // stage one input row (64 ch x 128 px) from pre-transformed g_x: pure copy
    auto stage = [&](int ky, int bufsel) {
        const float* base = g_x + ((size_t)(b * C_IN) * H + (y + ky)) * W + px0;
        unsigned dbase = xsb + (unsigned)bufsel * (C_IN * XR2 * 4);
#pragma unroll
        for (int q = 0; q < 8; q++) {
            int i = q * 256 + t;               // 0..2047
            int c = i >> 5, seg = i & 31;
            const float* src = base + (size_t)c * HW + seg * 4;
            unsigned dst = dbase + (unsigned)(c * XR2 + seg * 4) * 4u;
            asm volatile("cp.async.ca.shared.global [%0], [%1], 16;"
                         :: "r"(dst), "l"(src) : "memory");
        }
        asm volatile("cp.async.commit_group;" ::: "memory");
    };

    // acc[oct][nt][4]
    float acc[4][3][4];
#pragma unroll
    for (int o = 0; o < 4; o++)
#pragma unroll
        for (int nt = 0; nt < 3; nt++)
#pragma unroll
            for (int q = 0; q < 4; q++) acc[o][nt][q] = 0.f;

    const uint4* wbase = reinterpret_cast<const uint4*>(g_wA);

    stage(0, 0);

#pragma unroll 1
    for (int ky = 0; ky < 3; ky++) {
        asm volatile("cp.async.wait_group 0;" ::: "memory");
        __syncthreads();
        if (ky < 2) stage(ky + 1, (ky + 1) & 1);

        const float* Xb = Xs + (ky & 1) * (C_IN * XR2);

#pragma unroll 1
        for (int kx = 0; kx < 3; kx++) {
            const int tap = ky * 3 + kx;
            // uint4 index: tap*2048 + chunk*256 + slab*128 + oct*32 + lane
            const uint4* wp = wbase + tap * 2048 + slab * 128 + lane;
            const float* xr = Xb + (lane & 3) * XR2 + xb0 + kx + nb + (lane >> 2);

            uint4 an0 = wp[0];                 // prefetch chunk 0, all 4 octs
            uint4 an1 = wp[32];
            uint4 an2 = wp[64];
            uint4 an3 = wp[96];

#pragma unroll 1
            for (int ch = 0; ch < 8; ch++) {
                uint4 a0 = an0, a1 = an1, a2 = an2, a3 = an3;
                if (ch < 7) {
                    const uint4* wn = wp + (ch + 1) * 256;
                    an0 = wn[0];
                    an1 = wn[32];
                    an2 = wn[64];
                    an3 = wn[96];
                }
                const float* xc = xr + ch * (8 * XR2);
#pragma unroll
                for (int nt = 0; nt < 3; nt++) {
                    unsigned b0 = __float_as_uint(xc[nt * 8]);
                    unsigned b1 = __float_as_uint(xc[4 * XR2 + nt * 8]);
                    MMA_TF32(acc[0][nt], a0, b0, b1);
                    MMA_TF32(acc[1][nt], a1, b0, b1);
                    MMA_TF32(acc[2][nt], a2, b0, b1);
                    MMA_TF32(acc[3][nt], a3, b0, b1);
                }
            }
        }
    }

    // ---- epilogue: bias + store ------------------------------------------
    // D frag: d0:(m,2c) d1:(m,2c+1) d2:(m+8,2c) d3:(m+8,2c+1)
    const int mrow = lane >> 2;
    const int ncol = 2 * (lane & 3);
#pragma unroll
    for (int oct = 0; oct < 4; oct++) {
        int ocb = slab * 64 + oct * 16 + mrow;
        float bsA = g_bsum[b][ocb];
        float bsB = g_bsum[b][ocb + 8];
        float* o0 = out + ((size_t)(b * OC + ocb) * HO + y) * WO + x0 + nb + ncol;
        float* o1 = o0 + (size_t)8 * HO * WO;
#pragma unroll
        for (int nt = 0; nt < 3; nt++) {
            *reinterpret_cast<float2*>(o0 + nt * 8) =
                make_float2(acc[oct][nt][0] + bsA, acc[oct][nt][1] + bsA);
            *reinterpret_cast<float2*>(o1 + nt * 8) =
                make_float2(acc[oct][nt][2] + bsB, acc[oct][nt][3] + bsB);
        }
    }
}

// ---------------- launch -----------------------------------------------------
extern "C" void kernel_launch(void* const* d_in, const int* in_sizes, int n_in,
                              void* d_out, int out_size) {
    const float* x    = (const float*)d_in[0];
    const float* w    = (const float*)d_in[1];
    const float* bias = (const float*)d_in[2];
    float* out = (float*)d_out;

    const int SMEM_BYTES = 2 * C_IN * XR2 * 4;            // 67584 B
    cudaFuncSetAttribute(conv_kernel,
                         cudaFuncAttributeMaxDynamicSharedMemorySize, SMEM_BYTES);

    setup_kernel<<<289, 256>>>(x, w, bias);
    transform_kernel<<<dim3(36, 2048), 256>>>(x);
    conv_kernel<<<dim3(2, HO, B_N), 256, SMEM_BYTES>>>(out);
}

// round 13
// speedup vs baseline: 1.6544x; 1.6544x over previous
#include <cuda_runtime.h>
#include <cuda_fp16.h>
#include <cstdint>

#define B_N  32
#define C_IN 64
#define H    192
#define W    192
#define HO   190
#define WO   190
#define OC   128
#define HW   (H*W)

#define XSR  80           // conv SMEM px-row stride in fp16 (160B -> conflict-free LDS.64)
#define PXN  104          // staged px window

// ---------------- device scratch (static; no allocations allowed) -----------
__device__ float g_valid[B_N][4];
__device__ float g_bsum[B_N][OC];
// fp16 A-fragment weights: [tap][chunk(4)][slab(4)][oct(2)][lane(32)][reg(4)] as u32 (fp16x2)
__device__ __align__(16) unsigned g_wA[9 * 4 * 4 * 2 * 32 * 4];
// pre-transformed input, px-major quad-packed fp16: [b][y][px][cpos 64]
__device__ __align__(16) unsigned short g_x2[(size_t)B_N * H * W * C_IN];

__device__ __forceinline__ bool is_nan_bits(float v) {
    unsigned u = __float_as_uint(v);
    return (u & 0x7fffffffu) > 0x7f800000u;
}
__device__ __forceinline__ unsigned smem_u32(const void* p) {
    unsigned a;
    asm("{ .reg .u64 t; cvta.to.shared.u64 t, %1; cvt.u32.u64 %0, t; }" : "=r"(a) : "l"(p));
    return a;
}

#define MMA_F16(d, a, b0, b1) \
    asm volatile("mma.sync.aligned.m16n8k16.row.col.f32.f16.f16.f32 " \
        "{%0,%1,%2,%3},{%4,%5,%6,%7},{%8,%9},{%0,%1,%2,%3};" \
        : "+f"((d)[0]), "+f"((d)[1]), "+f"((d)[2]), "+f"((d)[3]) \
        : "r"((a).x), "r"((a).y), "r"((a).z), "r"((a).w), "r"(b0), "r"(b1))

// ---------------- setup: validity + bias + fp16 fragment weights ------------
// blocks 0..143: weights (36864 u32), block 144: validity + bias sums.
__global__ void setup_kernel(const float* __restrict__ x,
                             const float* __restrict__ w,
                             const float* __restrict__ bias) {
    int t = threadIdx.x;
    if (blockIdx.x < 144) {
        int i = blockIdx.x * 256 + t;            // 0..36863
        int reg  = i & 3;
        int lane = (i >> 2) & 31;
        int oct  = (i >> 7) & 1;
        int slab = (i >> 8) & 3;
        int chunk= (i >> 10) & 3;
        int tap  = i >> 12;                      // ky*3 + kx
        // fp16 m16n8k16 A frag: reg0:(m, 2k..2k+1) reg1:(m+8,·) reg2:(m, +8) reg3:(m+8,+8)
        int row = (lane >> 2) + (reg & 1) * 8;
        int kb  = 2 * (lane & 3) + (reg >> 1) * 8;
        int oc  = slab * 32 + oct * 16 + row;
        int c0  = chunk * 16 + kb;               // raw channel (lo half)
        int f0 = c0 & 3, j0 = c0 >> 2;
        int f1 = (c0 + 1) & 3, j1 = (c0 + 1) >> 2;
        float v0 = w[f0 * 18432 + oc * 144 + j0 * 9 + tap];
        float v1 = w[f1 * 18432 + oc * 144 + j1 * 9 + tap];
        unsigned h0 = __half_as_ushort(__float2half_rn(v0));
        unsigned h1 = __half_as_ushort(__float2half_rn(v1));
        g_wA[i] = h0 | (h1 << 16);
    } else {
        __shared__ float sval[B_N][4];
        if (t < B_N * 4) {
            int b = t >> 2, f = t & 3;
            float v = x[(size_t)(b * C_IN + f) * HW];   // marker at (0,0)
            float val = is_nan_bits(v) ? 0.f : 1.f;
            g_valid[b][f] = val;
            sval[b][f] = val;
        }
        __syncthreads();
        for (int i = t; i < B_N * OC; i += 256) {
            int b = i >> 7, oc = i & 127;
            float s = 0.f;
#pragma unroll
            for (int f = 0; f < 4; f++) s += sval[b][f] * bias[f * OC + oc];
            g_bsum[b][oc] = s;
        }
    }
}

// ---------------- transform: x -> g_x2 (mask + fp16 + px-major transpose) ---
// grid (192 y, 32 b), 256 threads. Quad-packed channel order within chunks of 16:
// cpos = chunk*16 + qi*4 + hi*2 + lo  for channel c = chunk*16 + qi*2 + lo + hi*8.
__global__ void transform_kernel(const float* __restrict__ x) {
    __shared__ unsigned short sT[64 * 202];
    __shared__ float vml[4];
    const int t = threadIdx.x, warp = t >> 5, lane = t & 31;
    const int y = blockIdx.x, b = blockIdx.y;

    if (t < 4) vml[t] = g_valid[b][t];
    __syncthreads();

#pragma unroll
    for (int q = 0; q < 8; q++) {
        int c = q * 8 + warp;
        float vmf = vml[c & 3];
        const float* src = x + ((size_t)(b * C_IN + c) * H + y) * W;
#pragma unroll
        for (int p = 0; p < 6; p++) {
            int px = lane + p * 32;
            float v = src[px];
            v = is_nan_bits(v) ? 0.f : v;
            sT[c * 202 + px] = __half_as_ushort(__float2half_rn(v * vmf));
        }
    }
    __syncthreads();

    unsigned* dst = reinterpret_cast<unsigned*>(g_x2) + ((size_t)(b * H + y) * W) * 32;
#pragma unroll
    for (int q = 0; q < 24; q++) {
        int idx = q * 256 + t;                   // 192 px * 32 u32
        int px = idx >> 5, cp2 = idx & 31;
        int cpos = 2 * cp2;                      // even cpos -> lo=0
        int chunk = cpos >> 4, p = cpos & 15;
        int qi = p >> 2, hi = (p >> 1) & 1;
        int c0 = chunk * 16 + qi * 2 + hi * 8;   // cpos+1 -> c0+1
        unsigned lo = sT[c0 * 202 + px];
        unsigned hh = sT[(c0 + 1) * 202 + px];
        dst[px * 32 + cp2] = lo | (hh << 16);
    }
}

// ---------------- main conv: fp16 m16n8k16 implicit GEMM --------------------
// grid = (2 x-tiles, 190 rows, 32 batches), block = 256 (8 warps)
// Block tile: 128 oc x 96 px. Warp: 32 oc x 48 px (slab=warp>>1, half=warp&1).
__global__ void __launch_bounds__(256, 2)
conv_kernel(float* __restrict__ out) {
    __shared__ unsigned short Xs[2][PXN * XSR];

    const int x0   = blockIdx.x * 94;          // output x start
    const int px0  = blockIdx.x * 88;          // staged window start
    const int xoff = x0 - px0;                 // 0 or 6
    const int y = blockIdx.y;
    const int b = blockIdx.z;

    const int t    = threadIdx.x;
    const int warp = t >> 5;
    const int lane = t & 31;
    const int slab = warp >> 1;                // oc slab of 32
    const int nb   = (warp & 1) * 48;          // px half

    // stage one input row: pure copy g_x2 -> SMEM (104 px x 128B, dst stride 160B)
    auto stage = [&](int ky, int bufsel) {
        const unsigned short* src =
            g_x2 + ((size_t)(b * H + (y + ky)) * W + px0) * 64;
        unsigned dbase = smem_u32(Xs[bufsel]);
#pragma unroll
        for (int q = 0; q < 4; q++) {
            int i = q * 256 + t;               // 832 x 16B
            if (i < PXN * 8) {
                int px = i >> 3, seg = i & 7;
                asm volatile("cp.async.ca.shared.global [%0], [%1], 16;"
                             :: "r"(dbase + (unsigned)(px * 160 + seg * 16)),
                                "l"(src + px * 64 + seg * 8) : "memory");
            }
        }
        asm volatile("cp.async.commit_group;" ::: "memory");
    };

    // acc[oct][nt][4]
    float acc[2][6][4];
#pragma unroll
    for (int o = 0; o < 2; o++)
#pragma unroll
        for (int nt = 0; nt < 6; nt++)
#pragma unroll
            for (int q = 0; q < 4; q++) acc[o][nt][q] = 0.f;

    const uint4* wbase = reinterpret_cast<const uint4*>(g_wA);

    stage(0, 0);

#pragma unroll 1
    for (int ky = 0; ky < 3; ky++) {
        asm volatile("cp.async.wait_group 0;" ::: "memory");
        __syncthreads();
        if (ky < 2) stage(ky + 1, (ky + 1) & 1);

        const unsigned short* Xb = Xs[ky & 1];

#pragma unroll 1
        for (int kx = 0; kx < 3; kx++) {
            const int tap = ky * 3 + kx;
            // uint4 idx: tap*1024 + chunk*256 + slab*64 + oct*32 + lane
            const uint4* wp = wbase + tap * 1024 + slab * 64 + lane;
            const unsigned short* xr =
                Xs[ky & 1] + (xoff + kx + nb + (lane >> 2)) * XSR + (lane & 3) * 4;

            uint4 an0 = wp[0];                 // prefetch chunk 0, both octs
            uint4 an1 = wp[32];

#pragma unroll 1
            for (int ch = 0; ch < 4; ch++) {
                uint4 a0 = an0, a1 = an1;
                if (ch < 3) {
                    an0 = wp[(ch + 1) * 256];
                    an1 = wp[(ch + 1) * 256 + 32];
                }
                const unsigned short* xc = xr + ch * 16;
#pragma unroll
                for (int nt = 0; nt < 6; nt++) {
                    unsigned long long bb =
                        *reinterpret_cast<const unsigned long long*>(xc + nt * (8 * XSR));
                    unsigned b0 = (unsigned)bb;
                    unsigned b1 = (unsigned)(bb >> 32);
                    MMA_F16(acc[0][nt], a0, b0, b1);
                    MMA_F16(acc[1][nt], a1, b0, b1);
                }
            }
            (void)Xb;
        }
    }

    // ---- epilogue: bias + store ------------------------------------------
    // D frag: d0:(m,2c) d1:(m,2c+1) d2:(m+8,2c) d3:(m+8,2c+1)
    const int mrow = lane >> 2;
    const int ncol = 2 * (lane & 3);
#pragma unroll
    for (int oct = 0; oct < 2; oct++) {
        int ocb = slab * 32 + oct * 16 + mrow;
        float bsA = g_bsum[b][ocb];
        float bsB = g_bsum[b][ocb + 8];
        float* o0 = out + ((size_t)(b * OC + ocb) * HO + y) * WO + x0 + nb + ncol;
        float* o1 = o0 + (size_t)8 * HO * WO;
#pragma unroll
        for (int nt = 0; nt < 6; nt++) {
            *reinterpret_cast<float2*>(o0 + nt * 8) =
                make_float2(acc[oct][nt][0] + bsA, acc[oct][nt][1] + bsA);
            *reinterpret_cast<float2*>(o1 + nt * 8) =
                make_float2(acc[oct][nt][2] + bsB, acc[oct][nt][3] + bsB);
        }
    }
}

// ---------------- launch -----------------------------------------------------
extern "C" void kernel_launch(void* const* d_in, const int* in_sizes, int n_in,
                              void* d_out, int out_size) {
    const float* x    = (const float*)d_in[0];
    const float* w    = (const float*)d_in[1];
    const float* bias = (const float*)d_in[2];
    float* out = (float*)d_out;

    setup_kernel<<<145, 256>>>(x, w, bias);
    transform_kernel<<<dim3(H, B_N), 256>>>(x);
    conv_kernel<<<dim3(2, HO, B_N), 256>>>(out);
}